// round 6
// baseline (speedup 1.0000x reference)
#include <cuda_runtime.h>

#define BB 128
#define LL 200
#define HH 128
#define CC 64

#define IS 132                    // smem stride (floats): 4 mod 32 -> conflict-free LDS.128
#define NROWS 64
#define SM_IN  (NROWS*IS)
#define SM_W   (HH*IS)
#define SMEM_BYTES ((SM_IN + SM_W) * 4)          // 101376 B
#define SCAN_SMEM  (LL*CC*4)                     // 51200 B

typedef unsigned long long u64;

// ---- scratch (static device globals; no allocations) ----
__device__ float g_K [BB*LL*CC];
__device__ float g_Qp[BB*LL*HH];
__device__ float g_E [BB*LL*HH];
__device__ float g_A [BB*LL*HH];
__device__ float g_R [BB*LL*HH];

__device__ __forceinline__ u64 fma2(u64 a, u64 b, u64 c) {
    u64 d; asm("fma.rn.f32x2 %0, %1, %2, %3;" : "=l"(d) : "l"(a), "l"(b), "l"(c));
    return d;
}
__device__ __forceinline__ u64 pack2(float lo, float hi) {
    u64 d; asm("mov.b64 %0, {%1, %2};" : "=l"(d) : "f"(lo), "f"(hi));
    return d;
}
__device__ __forceinline__ float2 unpack2(u64 a) {
    float2 f; asm("mov.b64 {%0, %1}, %2;" : "=f"(f.x), "=f"(f.y) : "l"(a));
    return f;
}
__device__ __forceinline__ float fast_tanh(float x) {
    float y; asm("tanh.approx.f32 %0, %1;" : "=f"(y) : "f"(x)); return y;
}
__device__ __forceinline__ float fast_sigmoid(float x) {
    return 1.f / (1.f + __expf(-x));
}

// stage a [rows x 128] row-major gmem matrix into smem with stride IS
__device__ __forceinline__ void stage(float* dst, const float* __restrict__ src,
                                      int rows, int tid, int nthr, int srcStride)
{
    for (int i = tid; i < rows*32; i += nthr) {
        int r = i >> 5, j = (i & 31) << 2;
        *(float4*)&dst[r*IS + j] = *(const float4*)&src[r*srcStride + j];
    }
}

// 64x128 GEMM core: thread tile 8 rows x 4 cols (cols = cx + 32k).
// Inner step: 4 j's via LDS.128 (ulonglong2 -> two f32x2 fma per load).
__device__ __forceinline__ void gemm4_8x4(const float* __restrict__ sIn,
                                          const float* __restrict__ sW,
                                          int ry, int cx, u64 acc[8][4])
{
    #pragma unroll
    for (int r = 0; r < 8; ++r)
        #pragma unroll
        for (int k = 0; k < 4; ++k) acc[r][k] = 0ull;

    const float* w0p = sW + (cx      )*IS;
    const float* w1p = sW + (cx + 32 )*IS;
    const float* w2p = sW + (cx + 64 )*IS;
    const float* w3p = sW + (cx + 96 )*IS;
    const float* qp  = sIn + ry*8*IS;

    #pragma unroll 4
    for (int j = 0; j < 128; j += 4) {
        ulonglong2 w0 = *(const ulonglong2*)(w0p + j);
        ulonglong2 w1 = *(const ulonglong2*)(w1p + j);
        ulonglong2 w2 = *(const ulonglong2*)(w2p + j);
        ulonglong2 w3 = *(const ulonglong2*)(w3p + j);
        #pragma unroll
        for (int r = 0; r < 8; ++r) {
            ulonglong2 q = *(const ulonglong2*)(qp + r*IS + j);
            acc[r][0] = fma2(q.x, w0.x, acc[r][0]);
            acc[r][1] = fma2(q.x, w1.x, acc[r][1]);
            acc[r][2] = fma2(q.x, w2.x, acc[r][2]);
            acc[r][3] = fma2(q.x, w3.x, acc[r][3]);
            acc[r][0] = fma2(q.y, w0.y, acc[r][0]);
            acc[r][1] = fma2(q.y, w1.y, acc[r][1]);
            acc[r][2] = fma2(q.y, w2.y, acc[r][2]);
            acc[r][3] = fma2(q.y, w3.y, acc[r][3]);
        }
    }
}

// ---------------- Kernel 1: fused precompute ---------------------------------
extern "C" __global__ void __launch_bounds__(256, 2)
k_pre(const int* __restrict__ X, const int* __restrict__ Q,
      const float* __restrict__ q_emb, const float* __restrict__ x_emb,
      const float* __restrict__ key_W,
      const float* __restrict__ p_W1, const float* __restrict__ p_b1,
      const float* __restrict__ e_W, const float* __restrict__ e_b,
      const float* __restrict__ a_W, const float* __restrict__ a_b)
{
    extern __shared__ float sm[];
    float* sIn = sm;
    float* sW  = sm + SM_IN;
    __shared__ int sIdx[NROWS];

    const int tid = threadIdx.x;
    const bool qk = blockIdx.x < 400;
    const int row0 = (qk ? blockIdx.x : blockIdx.x - 400) * NROWS;

    if (tid < NROWS) sIdx[tid] = (qk ? Q : X)[row0 + tid];
    __syncthreads();

    {   // stage 64 gathered embedding rows
        const float* emb = qk ? q_emb : x_emb;
        for (int i = tid; i < NROWS*32; i += 256) {
            int r = i >> 5, j = (i & 31) << 2;
            *(float4*)&sIn[r*IS + j] = *(const float4*)&emb[sIdx[r]*HH + j];
        }
    }

    if (qk) {
        // ---- logits + softmax: 64x64, tile 4x4 (cols cx + 16k) ----
        stage(sW, key_W, CC, tid, 256, HH);
        __syncthreads();
        {
            const int cx = tid & 15;
            const int ry = tid >> 4;
            u64 acc[4][4];
            #pragma unroll
            for (int r = 0; r < 4; ++r)
                #pragma unroll
                for (int k = 0; k < 4; ++k) acc[r][k] = 0ull;

            const float* w0p = sW + (cx      )*IS;
            const float* w1p = sW + (cx + 16 )*IS;
            const float* w2p = sW + (cx + 32 )*IS;
            const float* w3p = sW + (cx + 48 )*IS;
            const float* qp  = sIn + ry*4*IS;

            #pragma unroll 4
            for (int j = 0; j < 128; j += 4) {
                ulonglong2 w0 = *(const ulonglong2*)(w0p + j);
                ulonglong2 w1 = *(const ulonglong2*)(w1p + j);
                ulonglong2 w2 = *(const ulonglong2*)(w2p + j);
                ulonglong2 w3 = *(const ulonglong2*)(w3p + j);
                #pragma unroll
                for (int r = 0; r < 4; ++r) {
                    ulonglong2 q = *(const ulonglong2*)(qp + r*IS + j);
                    acc[r][0] = fma2(q.x, w0.x, acc[r][0]);
                    acc[r][1] = fma2(q.x, w1.x, acc[r][1]);
                    acc[r][2] = fma2(q.x, w2.x, acc[r][2]);
                    acc[r][3] = fma2(q.x, w3.x, acc[r][3]);
                    acc[r][0] = fma2(q.y, w0.y, acc[r][0]);
                    acc[r][1] = fma2(q.y, w1.y, acc[r][1]);
                    acc[r][2] = fma2(q.y, w2.y, acc[r][2]);
                    acc[r][3] = fma2(q.y, w3.y, acc[r][3]);
                }
            }
            #pragma unroll
            for (int r = 0; r < 4; ++r) {
                float v[4];
                #pragma unroll
                for (int k = 0; k < 4; ++k) {
                    float2 f = unpack2(acc[r][k]);
                    v[k] = f.x + f.y;
                }
                float mx = fmaxf(fmaxf(v[0], v[1]), fmaxf(v[2], v[3]));
                #pragma unroll
                for (int off = 8; off >= 1; off >>= 1)
                    mx = fmaxf(mx, __shfl_xor_sync(0xffffffffu, mx, off));
                float e0 = __expf(v[0]-mx), e1 = __expf(v[1]-mx);
                float e2 = __expf(v[2]-mx), e3 = __expf(v[3]-mx);
                float sum = (e0+e1) + (e2+e3);
                #pragma unroll
                for (int off = 8; off >= 1; off >>= 1)
                    sum += __shfl_xor_sync(0xffffffffu, sum, off);
                float inv = __frcp_rn(sum);
                float* o = &g_K[(row0 + ry*4 + r)*CC + cx];
                o[0]  = e0*inv; o[16] = e1*inv; o[32] = e2*inv; o[48] = e3*inv;
            }
        }
        __syncthreads();

        // ---- Qproj = Qe @ W1q.T + b1 ----
        stage(sW, p_W1, HH, tid, 256, 256);     // W1q = p_W1[:, :128]
        __syncthreads();
        {
            const int cx = tid & 31, ry = tid >> 5;
            u64 acc[8][4];
            gemm4_8x4(sIn, sW, ry, cx, acc);
            float b[4] = { p_b1[cx], p_b1[cx+32], p_b1[cx+64], p_b1[cx+96] };
            #pragma unroll
            for (int r = 0; r < 8; ++r) {
                float* o = &g_Qp[(row0 + ry*8 + r)*HH + cx];
                #pragma unroll
                for (int k = 0; k < 4; ++k) {
                    float2 f = unpack2(acc[r][k]);
                    o[k*32] = f.x + f.y + b[k];
                }
            }
        }
    } else {
        const int cx = tid & 31, ry = tid >> 5;
        // ---- E = sigmoid(Xe@e_W.T + e_b) ----
        stage(sW, e_W, HH, tid, 256, HH);
        __syncthreads();
        {
            u64 acc[8][4];
            gemm4_8x4(sIn, sW, ry, cx, acc);
            float b[4] = { e_b[cx], e_b[cx+32], e_b[cx+64], e_b[cx+96] };
            #pragma unroll
            for (int r = 0; r < 8; ++r) {
                float* o = &g_E[(row0 + ry*8 + r)*HH + cx];
                #pragma unroll
                for (int k = 0; k < 4; ++k) {
                    float2 f = unpack2(acc[r][k]);
                    o[k*32] = fast_sigmoid(f.x + f.y + b[k]);
                }
            }
        }
        __syncthreads();
        // ---- A = tanh(Xe@a_W.T + a_b) ----
        stage(sW, a_W, HH, tid, 256, HH);
        __syncthreads();
        {
            u64 acc[8][4];
            gemm4_8x4(sIn, sW, ry, cx, acc);
            float b[4] = { a_b[cx], a_b[cx+32], a_b[cx+64], a_b[cx+96] };
            #pragma unroll
            for (int r = 0; r < 8; ++r) {
                float* o = &g_A[(row0 + ry*8 + r)*HH + cx];
                #pragma unroll
                for (int k = 0; k < 4; ++k) {
                    float2 f = unpack2(acc[r][k]);
                    o[k*32] = fast_tanh(f.x + f.y + b[k]);
                }
            }
        }
    }
}

// ---------------- Kernel 2: the scan -----------------------------------------
// 256 blocks x 256 thr. block = (b, 64 h's). K staged in smem once per block;
// all warps read it via broadcast LDS. m in registers; E/A prefetched.
extern "C" __global__ void __launch_bounds__(256, 2)
k_scan()
{
    extern __shared__ float sK[];     // 200 x 64

    const int tid  = threadIdx.x;
    const int b    = blockIdx.x >> 1;
    const int hblk = blockIdx.x & 1;

    {   // cooperative K stage (coalesced float4)
        const float4* src = (const float4*)(g_K + b*LL*CC);
        float4* dst = (float4*)sK;
        #pragma unroll 4
        for (int i = tid; i < LL*CC/4; i += 256) dst[i] = src[i];
    }
    __syncthreads();

    const int wid  = tid >> 5;
    const int lane = tid & 31;
    const int sub  = lane >> 2;
    const int g    = lane & 3;
    const int h    = hblk*64 + wid*8 + sub;

    const float* Ks = sK + g*16;
    const float* Eb = g_E + b*LL*HH + h;
    const float* Ab = g_A + b*LL*HH + h;
    float*       Rb = g_R + b*LL*HH + h;

    u64 m2[8];
    #pragma unroll
    for (int i = 0; i < 8; ++i) m2[i] = 0ull;

    float ec = Eb[0], ac = Ab[0];

    #pragma unroll 2
    for (int t = 0; t < LL; ++t) {
        // prefetch next-step E/A (gmem); K comes from smem (low latency)
        const int tn = (t + 1 < LL) ? t + 1 : t;
        float en = Eb[tn*HH];
        float an = Ab[tn*HH];

        u64 kc[8];
        {
            const ulonglong2* p = (const ulonglong2*)(Ks + t*CC);
            ulonglong2 a0 = p[0], a1 = p[1], a2 = p[2], a3 = p[3];
            kc[0]=a0.x; kc[1]=a0.y; kc[2]=a1.x; kc[3]=a1.y;
            kc[4]=a2.x; kc[5]=a2.y; kc[6]=a3.x; kc[7]=a3.y;
        }

        // dot: R = sum_c k*m
        u64 sA = 0ull, sB = 0ull;
        #pragma unroll
        for (int i = 0; i < 4; ++i) {
            sA = fma2(kc[i],   m2[i],   sA);
            sB = fma2(kc[i+4], m2[i+4], sB);
        }
        float2 fa = unpack2(sA), fb = unpack2(sB);
        float s = (fa.x + fa.y) + (fb.x + fb.y);
        s += __shfl_xor_sync(0xffffffffu, s, 1);
        s += __shfl_xor_sync(0xffffffffu, s, 2);
        if (g == 0) Rb[t*HH] = s;

        // update: m = m + k*(a - m*e)
        u64 nee = pack2(-ec, -ec);
        u64 aa2 = pack2( ac,  ac);
        #pragma unroll
        for (int i = 0; i < 8; ++i)
            m2[i] = fma2(kc[i], fma2(m2[i], nee, aa2), m2[i]);

        ec = en; ac = an;
    }
}

// ---------------- Kernel 3: P = sigmoid(tanh(Qp + R@W1r.T) . pW2 + b2) -------
extern "C" __global__ void __launch_bounds__(256, 2)
k_out(const float* __restrict__ p_W1, const float* __restrict__ p_W2,
      const float* __restrict__ p_b2, float* __restrict__ out)
{
    extern __shared__ float sm[];
    float* sR = sm;             // 64 x 132
    float* sW = sm + SM_IN;     // 128 x 132 (W1r)
    __shared__ float sW2[HH];

    const int tid  = threadIdx.x;
    const int row0 = blockIdx.x * NROWS;

    if (tid < HH) sW2[tid] = p_W2[tid];
    for (int i = tid; i < NROWS*32; i += 256) {
        int r = i >> 5, j = (i & 31) << 2;
        *(float4*)&sR[r*IS + j] = *(const float4*)&g_R[(row0 + r)*HH + j];
    }
    stage(sW, p_W1 + 128, HH, tid, 256, 256);   // W1r = p_W1[:, 128:]
    __syncthreads();

    const int cx = tid & 31, ry = tid >> 5;
    u64 acc[8][4];
    gemm4_8x4(sR, sW, ry, cx, acc);

    const float b2v = __ldg(p_b2);
    float w2c[4] = { sW2[cx], sW2[cx+32], sW2[cx+64], sW2[cx+96] };

    #pragma unroll
    for (int r = 0; r < 8; ++r) {
        int row = row0 + ry*8 + r;
        const float* qp = &g_Qp[row*HH + cx];
        float ps = 0.f;
        #pragma unroll
        for (int k = 0; k < 4; ++k) {
            float2 f = unpack2(acc[r][k]);
            ps = fmaf(fast_tanh(f.x + f.y + qp[k*32]), w2c[k], ps);
        }
        #pragma unroll
        for (int off = 16; off >= 1; off >>= 1)
            ps += __shfl_xor_sync(0xffffffffu, ps, off);
        if ((tid & 31) == 0)
            out[row] = fast_sigmoid(ps + b2v);
    }
}

// ---------------- launch ----------------
extern "C" void kernel_launch(void* const* d_in, const int* in_sizes, int n_in,
                              void* d_out, int out_size)
{
    const int*   X     = (const int*)  d_in[0];
    const int*   Q     = (const int*)  d_in[1];
    const float* q_emb = (const float*)d_in[2];
    const float* x_emb = (const float*)d_in[3];
    const float* key_W = (const float*)d_in[4];
    const float* p_W1  = (const float*)d_in[5];
    const float* p_b1  = (const float*)d_in[6];
    const float* p_W2  = (const float*)d_in[7];
    const float* p_b2  = (const float*)d_in[8];
    const float* e_W   = (const float*)d_in[9];
    const float* e_b   = (const float*)d_in[10];
    const float* a_W   = (const float*)d_in[11];
    const float* a_b   = (const float*)d_in[12];
    float* out = (float*)d_out;

    static int configured = 0;
    if (!configured) {
        cudaFuncSetAttribute(k_pre,  cudaFuncAttributeMaxDynamicSharedMemorySize, SMEM_BYTES);
        cudaFuncSetAttribute(k_scan, cudaFuncAttributeMaxDynamicSharedMemorySize, SCAN_SMEM);
        cudaFuncSetAttribute(k_out,  cudaFuncAttributeMaxDynamicSharedMemorySize, SMEM_BYTES);
        configured = 1;
    }

    k_pre <<<800, 256, SMEM_BYTES>>>(X, Q, q_emb, x_emb, key_W,
                                     p_W1, p_b1, e_W, e_b, a_W, a_b);
    k_scan<<<BB*2, 256, SCAN_SMEM>>>();
    k_out <<<400, 256, SMEM_BYTES>>>(p_W1, p_W2, p_b2, out);
}

// round 7
// speedup vs baseline: 1.0344x; 1.0344x over previous
#include <cuda_runtime.h>
#include <cstdint>

#define BB 128
#define LL 200
#define HH 128
#define CC 64

#define IS 132                    // smem stride: 4 mod 32 -> conflict-free LDS.128
#define NROWS 64
#define SM_IN  (NROWS*IS)         // input tile floats
#define SM_P   (64*IS)            // one 64-row weight panel
#define PRE_SMEM ((SM_IN + 2*SM_P) * 4)          // 101376 B -> 2 CTAs/SM
#define SM_W   (HH*IS)
#define OUT_SMEM ((SM_IN + SM_W) * 4)            // 101376 B
#define SCAN_SMEM (LL*CC*4)                      // 51200 B

typedef unsigned long long u64;

// ---- scratch (static device globals; no allocations) ----
__device__ float g_K [BB*LL*CC];
__device__ float g_Qp[BB*LL*HH];
__device__ float g_E [BB*LL*HH];
__device__ float g_A [BB*LL*HH];
__device__ float g_R [BB*LL*HH];

__device__ __forceinline__ u64 fma2(u64 a, u64 b, u64 c) {
    u64 d; asm("fma.rn.f32x2 %0, %1, %2, %3;" : "=l"(d) : "l"(a), "l"(b), "l"(c));
    return d;
}
__device__ __forceinline__ float2 unpack2(u64 a) {
    float2 f; asm("mov.b64 {%0, %1}, %2;" : "=f"(f.x), "=f"(f.y) : "l"(a));
    return f;
}
__device__ __forceinline__ u64 pack2(float lo, float hi) {
    u64 d; asm("mov.b64 %0, {%1, %2};" : "=l"(d) : "f"(lo), "f"(hi));
    return d;
}
__device__ __forceinline__ float fast_tanh(float x) {
    float y; asm("tanh.approx.f32 %0, %1;" : "=f"(y) : "f"(x)); return y;
}
__device__ __forceinline__ float fast_sigmoid(float x) {
    return 1.f / (1.f + __expf(-x));
}
__device__ __forceinline__ void cp16(float* smem_dst, const float* gsrc) {
    uint32_t s = (uint32_t)__cvta_generic_to_shared(smem_dst);
    asm volatile("cp.async.ca.shared.global [%0], [%1], 16;" :: "r"(s), "l"(gsrc));
}
#define CP_COMMIT() asm volatile("cp.async.commit_group;")
#define CP_WAIT0()  asm volatile("cp.async.wait_group 0;" ::: "memory")

// async-copy one 64x128 weight panel (row stride `stride`) into smem stride IS
__device__ __forceinline__ void cp_panel(float* dst, const float* __restrict__ src,
                                         int stride, int tid)
{
    #pragma unroll
    for (int s = 0; s < 8; ++s) {
        int i = tid + s*256;
        int r = i >> 5, j = (i & 31) << 2;
        cp16(&dst[r*IS + j], &src[r*stride + j]);
    }
}

// 64x64 panel GEMM: 256 thr = 16x16 grid, thread tile 4 rows x 4 cols (cx+16k).
__device__ __forceinline__ void gemm_panel(const float* __restrict__ sIn,
                                           const float* __restrict__ sP,
                                           int ry, int cx, u64 acc[4][4])
{
    #pragma unroll
    for (int r = 0; r < 4; ++r)
        #pragma unroll
        for (int k = 0; k < 4; ++k) acc[r][k] = 0ull;

    const float* w0p = sP + (cx      )*IS;
    const float* w1p = sP + (cx + 16 )*IS;
    const float* w2p = sP + (cx + 32 )*IS;
    const float* w3p = sP + (cx + 48 )*IS;
    const float* qp  = sIn + ry*4*IS;

    #pragma unroll 8
    for (int j = 0; j < 128; j += 4) {
        ulonglong2 w0 = *(const ulonglong2*)(w0p + j);
        ulonglong2 w1 = *(const ulonglong2*)(w1p + j);
        ulonglong2 w2 = *(const ulonglong2*)(w2p + j);
        ulonglong2 w3 = *(const ulonglong2*)(w3p + j);
        #pragma unroll
        for (int r = 0; r < 4; ++r) {
            ulonglong2 q = *(const ulonglong2*)(qp + r*IS + j);
            acc[r][0] = fma2(q.x, w0.x, acc[r][0]);
            acc[r][1] = fma2(q.x, w1.x, acc[r][1]);
            acc[r][2] = fma2(q.x, w2.x, acc[r][2]);
            acc[r][3] = fma2(q.x, w3.x, acc[r][3]);
            acc[r][0] = fma2(q.y, w0.y, acc[r][0]);
            acc[r][1] = fma2(q.y, w1.y, acc[r][1]);
            acc[r][2] = fma2(q.y, w2.y, acc[r][2]);
            acc[r][3] = fma2(q.y, w3.y, acc[r][3]);
        }
    }
}

// ---------------- Kernel 1: cp.async-pipelined precompute --------------------
// blocks [0,400):  panels = [key_W | W1q(0:64) | W1q(64:128)] over Qe
// blocks [400,800): panels = [e_W(0:64) | e_W(64:128) | a_W(0:64) | a_W(64:128)] over Xe
extern "C" __global__ void __launch_bounds__(256, 2)
k_pre(const int* __restrict__ X, const int* __restrict__ Q,
      const float* __restrict__ q_emb, const float* __restrict__ x_emb,
      const float* __restrict__ key_W,
      const float* __restrict__ p_W1, const float* __restrict__ p_b1,
      const float* __restrict__ e_W, const float* __restrict__ e_b,
      const float* __restrict__ a_W, const float* __restrict__ a_b)
{
    extern __shared__ float sm[];
    float* sIn = sm;
    float* sPb[2] = { sm + SM_IN, sm + SM_IN + SM_P };
    __shared__ int sIdx[NROWS];

    const int tid = threadIdx.x;
    const bool qk = blockIdx.x < 400;
    const int row0 = (qk ? blockIdx.x : blockIdx.x - 400) * NROWS;

    if (tid < NROWS) sIdx[tid] = (qk ? Q : X)[row0 + tid];
    __syncthreads();

    // async input gather (64 rows) + panel 0
    {
        const float* emb = qk ? q_emb : x_emb;
        #pragma unroll
        for (int s = 0; s < 8; ++s) {
            int i = tid + s*256;
            int r = i >> 5, j = (i & 31) << 2;
            cp16(&sIn[r*IS + j], &emb[sIdx[r]*HH + j]);
        }
    }

    const float* psrc[4];
    int pstr[4], P;
    if (qk) {
        psrc[0] = key_W;           pstr[0] = HH;
        psrc[1] = p_W1;            pstr[1] = 256;
        psrc[2] = p_W1 + 64*256;   pstr[2] = 256;
        P = 3;
    } else {
        psrc[0] = e_W;             pstr[0] = HH;
        psrc[1] = e_W + 64*HH;     pstr[1] = HH;
        psrc[2] = a_W;             pstr[2] = HH;
        psrc[3] = a_W + 64*HH;     pstr[3] = HH;
        P = 4;
    }
    cp_panel(sPb[0], psrc[0], pstr[0], tid);
    CP_COMMIT();

    const int cx = tid & 15;
    const int ry = tid >> 4;

    for (int p = 0; p < P; ++p) {
        CP_WAIT0();
        __syncthreads();
        if (p + 1 < P) {
            cp_panel(sPb[(p+1)&1], psrc[p+1], pstr[p+1], tid);
            CP_COMMIT();
        }

        u64 acc[4][4];
        gemm_panel(sIn, sPb[p&1], ry, cx, acc);

        if (qk) {
            if (p == 0) {
                // softmax over the 64 key columns
                #pragma unroll
                for (int r = 0; r < 4; ++r) {
                    float v[4];
                    #pragma unroll
                    for (int k = 0; k < 4; ++k) {
                        float2 f = unpack2(acc[r][k]);
                        v[k] = f.x + f.y;
                    }
                    float mx = fmaxf(fmaxf(v[0], v[1]), fmaxf(v[2], v[3]));
                    #pragma unroll
                    for (int off = 8; off >= 1; off >>= 1)
                        mx = fmaxf(mx, __shfl_xor_sync(0xffffffffu, mx, off));
                    float e0 = __expf(v[0]-mx), e1 = __expf(v[1]-mx);
                    float e2 = __expf(v[2]-mx), e3 = __expf(v[3]-mx);
                    float sum = (e0+e1) + (e2+e3);
                    #pragma unroll
                    for (int off = 8; off >= 1; off >>= 1)
                        sum += __shfl_xor_sync(0xffffffffu, sum, off);
                    float inv = __frcp_rn(sum);
                    float* o = &g_K[(row0 + ry*4 + r)*CC + cx];
                    o[0]  = e0*inv; o[16] = e1*inv; o[32] = e2*inv; o[48] = e3*inv;
                }
            } else {
                const int col0 = (p - 1) * 64;
                #pragma unroll
                for (int r = 0; r < 4; ++r) {
                    float* o = &g_Qp[(row0 + ry*4 + r)*HH + col0 + cx];
                    #pragma unroll
                    for (int k = 0; k < 4; ++k) {
                        float2 f = unpack2(acc[r][k]);
                        o[k*16] = f.x + f.y + p_b1[col0 + cx + k*16];
                    }
                }
            }
        } else {
            if (p < 2) {
                const int col0 = p * 64;
                #pragma unroll
                for (int r = 0; r < 4; ++r) {
                    float* o = &g_E[(row0 + ry*4 + r)*HH + col0 + cx];
                    #pragma unroll
                    for (int k = 0; k < 4; ++k) {
                        float2 f = unpack2(acc[r][k]);
                        o[k*16] = fast_sigmoid(f.x + f.y + e_b[col0 + cx + k*16]);
                    }
                }
            } else {
                const int col0 = (p - 2) * 64;
                #pragma unroll
                for (int r = 0; r < 4; ++r) {
                    float* o = &g_A[(row0 + ry*4 + r)*HH + col0 + cx];
                    #pragma unroll
                    for (int k = 0; k < 4; ++k) {
                        float2 f = unpack2(acc[r][k]);
                        o[k*16] = fast_tanh(f.x + f.y + a_b[col0 + cx + k*16]);
                    }
                }
            }
        }
    }
}

// ---------------- Kernel 2: the scan -----------------------------------------
// 256 blocks x 256 thr. block = (b, 64 h's). K staged in smem once per block.
extern "C" __global__ void __launch_bounds__(256, 2)
k_scan()
{
    extern __shared__ float sK[];     // 200 x 64

    const int tid  = threadIdx.x;
    const int b    = blockIdx.x >> 1;
    const int hblk = blockIdx.x & 1;

    {   // cooperative K stage (coalesced float4)
        const float4* src = (const float4*)(g_K + b*LL*CC);
        float4* dst = (float4*)sK;
        #pragma unroll 4
        for (int i = tid; i < LL*CC/4; i += 256) dst[i] = src[i];
    }
    __syncthreads();

    const int wid  = tid >> 5;
    const int lane = tid & 31;
    const int sub  = lane >> 2;
    const int g    = lane & 3;
    const int h    = hblk*64 + wid*8 + sub;

    const float* Ks = sK + g*16;
    const float* Eb = g_E + b*LL*HH + h;
    const float* Ab = g_A + b*LL*HH + h;
    float*       Rb = g_R + b*LL*HH + h;

    u64 m2[8];
    #pragma unroll
    for (int i = 0; i < 8; ++i) m2[i] = 0ull;

    float ec = Eb[0], ac = Ab[0];

    #pragma unroll 2
    for (int t = 0; t < LL; ++t) {
        const int tn = (t + 1 < LL) ? t + 1 : t;
        float en = Eb[tn*HH];
        float an = Ab[tn*HH];

        u64 kc[8];
        {
            const ulonglong2* p = (const ulonglong2*)(Ks + t*CC);
            ulonglong2 a0 = p[0], a1 = p[1], a2 = p[2], a3 = p[3];
            kc[0]=a0.x; kc[1]=a0.y; kc[2]=a1.x; kc[3]=a1.y;
            kc[4]=a2.x; kc[5]=a2.y; kc[6]=a3.x; kc[7]=a3.y;
        }

        u64 sA = 0ull, sB = 0ull;
        #pragma unroll
        for (int i = 0; i < 4; ++i) {
            sA = fma2(kc[i],   m2[i],   sA);
            sB = fma2(kc[i+4], m2[i+4], sB);
        }
        float2 fa = unpack2(sA), fb = unpack2(sB);
        float s = (fa.x + fa.y) + (fb.x + fb.y);
        s += __shfl_xor_sync(0xffffffffu, s, 1);
        s += __shfl_xor_sync(0xffffffffu, s, 2);
        if (g == 0) Rb[t*HH] = s;

        u64 nee = pack2(-ec, -ec);
        u64 aa2 = pack2( ac,  ac);
        #pragma unroll
        for (int i = 0; i < 8; ++i)
            m2[i] = fma2(kc[i], fma2(m2[i], nee, aa2), m2[i]);

        ec = en; ac = an;
    }
}

// ---------------- Kernel 3: P = sigmoid(tanh(Qp + R@W1r.T) . pW2 + b2) -------
extern "C" __global__ void __launch_bounds__(256, 2)
k_out(const float* __restrict__ p_W1, const float* __restrict__ p_W2,
      const float* __restrict__ p_b2, float* __restrict__ out)
{
    extern __shared__ float sm[];
    float* sR = sm;             // 64 x 132
    float* sW = sm + SM_IN;     // 128 x 132 (W1r)
    __shared__ float sW2[HH];

    const int tid  = threadIdx.x;
    const int row0 = blockIdx.x * NROWS;

    if (tid < HH) sW2[tid] = p_W2[tid];
    for (int i = tid; i < NROWS*32; i += 256) {
        int r = i >> 5, j = (i & 31) << 2;
        *(float4*)&sR[r*IS + j] = *(const float4*)&g_R[(row0 + r)*HH + j];
    }
    for (int i = tid; i < HH*32; i += 256) {
        int r = i >> 5, j = (i & 31) << 2;
        *(float4*)&sW[r*IS + j] = *(const float4*)&p_W1[r*256 + 128 + j];
    }
    __syncthreads();

    const int cx = tid & 31, ry = tid >> 5;
    u64 acc[8][4];
    {
        #pragma unroll
        for (int r = 0; r < 8; ++r)
            #pragma unroll
            for (int k = 0; k < 4; ++k) acc[r][k] = 0ull;

        const float* w0p = sW + (cx      )*IS;
        const float* w1p = sW + (cx + 32 )*IS;
        const float* w2p = sW + (cx + 64 )*IS;
        const float* w3p = sW + (cx + 96 )*IS;
        const float* qp  = sR + ry*8*IS;

        #pragma unroll 4
        for (int j = 0; j < 128; j += 4) {
            ulonglong2 w0 = *(const ulonglong2*)(w0p + j);
            ulonglong2 w1 = *(const ulonglong2*)(w1p + j);
            ulonglong2 w2 = *(const ulonglong2*)(w2p + j);
            ulonglong2 w3 = *(const ulonglong2*)(w3p + j);
            #pragma unroll
            for (int r = 0; r < 8; ++r) {
                ulonglong2 q = *(const ulonglong2*)(qp + r*IS + j);
                acc[r][0] = fma2(q.x, w0.x, acc[r][0]);
                acc[r][1] = fma2(q.x, w1.x, acc[r][1]);
                acc[r][2] = fma2(q.x, w2.x, acc[r][2]);
                acc[r][3] = fma2(q.x, w3.x, acc[r][3]);
                acc[r][0] = fma2(q.y, w0.y, acc[r][0]);
                acc[r][1] = fma2(q.y, w1.y, acc[r][1]);
                acc[r][2] = fma2(q.y, w2.y, acc[r][2]);
                acc[r][3] = fma2(q.y, w3.y, acc[r][3]);
            }
        }
    }

    const float b2v = __ldg(p_b2);
    float w2c[4] = { sW2[cx], sW2[cx+32], sW2[cx+64], sW2[cx+96] };

    #pragma unroll
    for (int r = 0; r < 8; ++r) {
        int row = row0 + ry*8 + r;
        const float* qp = &g_Qp[row*HH + cx];
        float ps = 0.f;
        #pragma unroll
        for (int k = 0; k < 4; ++k) {
            float2 f = unpack2(acc[r][k]);
            ps = fmaf(fast_tanh(f.x + f.y + qp[k*32]), w2c[k], ps);
        }
        #pragma unroll
        for (int off = 16; off >= 1; off >>= 1)
            ps += __shfl_xor_sync(0xffffffffu, ps, off);
        if ((tid & 31) == 0)
            out[row] = fast_sigmoid(ps + b2v);
    }
}

// ---------------- launch ----------------
extern "C" void kernel_launch(void* const* d_in, const int* in_sizes, int n_in,
                              void* d_out, int out_size)
{
    const int*   X     = (const int*)  d_in[0];
    const int*   Q     = (const int*)  d_in[1];
    const float* q_emb = (const float*)d_in[2];
    const float* x_emb = (const float*)d_in[3];
    const float* key_W = (const float*)d_in[4];
    const float* p_W1  = (const float*)d_in[5];
    const float* p_b1  = (const float*)d_in[6];
    const float* p_W2  = (const float*)d_in[7];
    const float* p_b2  = (const float*)d_in[8];
    const float* e_W   = (const float*)d_in[9];
    const float* e_b   = (const float*)d_in[10];
    const float* a_W   = (const float*)d_in[11];
    const float* a_b   = (const float*)d_in[12];
    float* out = (float*)d_out;

    static int configured = 0;
    if (!configured) {
        cudaFuncSetAttribute(k_pre,  cudaFuncAttributeMaxDynamicSharedMemorySize, PRE_SMEM);
        cudaFuncSetAttribute(k_scan, cudaFuncAttributeMaxDynamicSharedMemorySize, SCAN_SMEM);
        cudaFuncSetAttribute(k_out,  cudaFuncAttributeMaxDynamicSharedMemorySize, OUT_SMEM);
        configured = 1;
    }

    k_pre <<<800, 256, PRE_SMEM>>>(X, Q, q_emb, x_emb, key_W,
                                   p_W1, p_b1, e_W, e_b, a_W, a_b);
    k_scan<<<BB*2, 256, SCAN_SMEM>>>();
    k_out <<<400, 256, OUT_SMEM>>>(p_W1, p_W2, p_b2, out);
}

// round 10
// speedup vs baseline: 1.0345x; 1.0002x over previous
#include <cuda_runtime.h>
#include <cstdint>

#define BB 128
#define LL 200
#define HH 128
#define CC 64

#define IS 132                    // smem stride: 4 mod 32 -> conflict-free LDS.128
#define NROWS 64
#define SM_IN  (NROWS*IS)         // input tile floats
#define SM_P   (64*IS)            // one 64-row weight panel
#define PRE_SMEM ((SM_IN + 2*SM_P) * 4)          // 101376 B -> 2 CTAs/SM
#define SM_W   (HH*IS)
#define OUT_SMEM ((SM_IN + SM_W) * 4)            // 101376 B
#define SCAN_SMEM (LL*CC*4)                      // 51200 B

typedef unsigned long long u64;

// ---- scratch (static device globals; no allocations) ----
__device__ float g_K [BB*LL*CC];
__device__ float g_Qp[BB*LL*HH];
__device__ float g_E [BB*LL*HH];
__device__ float g_A [BB*LL*HH];
__device__ float g_R [BB*LL*HH];

__device__ __forceinline__ u64 fma2(u64 a, u64 b, u64 c) {
    u64 d; asm("fma.rn.f32x2 %0, %1, %2, %3;" : "=l"(d) : "l"(a), "l"(b), "l"(c));
    return d;
}
__device__ __forceinline__ float2 unpack2(u64 a) {
    float2 f; asm("mov.b64 {%0, %1}, %2;" : "=f"(f.x), "=f"(f.y) : "l"(a));
    return f;
}
__device__ __forceinline__ u64 pack2(float lo, float hi) {
    u64 d; asm("mov.b64 %0, {%1, %2};" : "=l"(d) : "f"(lo), "f"(hi));
    return d;
}
__device__ __forceinline__ float fast_tanh(float x) {
    float y; asm("tanh.approx.f32 %0, %1;" : "=f"(y) : "f"(x)); return y;
}
__device__ __forceinline__ float fast_sigmoid(float x) {
    return 1.f / (1.f + __expf(-x));
}
__device__ __forceinline__ void cp16(float* smem_dst, const float* gsrc) {
    uint32_t s = (uint32_t)__cvta_generic_to_shared(smem_dst);
    asm volatile("cp.async.ca.shared.global [%0], [%1], 16;" :: "r"(s), "l"(gsrc));
}
#define CP_COMMIT() asm volatile("cp.async.commit_group;")
#define CP_WAIT0()  asm volatile("cp.async.wait_group 0;" ::: "memory")

// async-copy one 64x128 weight panel (row stride `stride`) into smem stride IS
__device__ __forceinline__ void cp_panel(float* dst, const float* __restrict__ src,
                                         int stride, int tid)
{
    #pragma unroll
    for (int s = 0; s < 8; ++s) {
        int i = tid + s*256;
        int r = i >> 5, j = (i & 31) << 2;
        cp16(&dst[r*IS + j], &src[r*stride + j]);
    }
}

// 64x64 panel GEMM: 256 thr = 16x16 grid, thread tile 4 rows x 4 cols (cx+16k).
__device__ __forceinline__ void gemm_panel(const float* __restrict__ sIn,
                                           const float* __restrict__ sP,
                                           int ry, int cx, u64 acc[4][4])
{
    #pragma unroll
    for (int r = 0; r < 4; ++r)
        #pragma unroll
        for (int k = 0; k < 4; ++k) acc[r][k] = 0ull;

    const float* w0p = sP + (cx      )*IS;
    const float* w1p = sP + (cx + 16 )*IS;
    const float* w2p = sP + (cx + 32 )*IS;
    const float* w3p = sP + (cx + 48 )*IS;
    const float* qp  = sIn + ry*4*IS;

    #pragma unroll 8
    for (int j = 0; j < 128; j += 4) {
        ulonglong2 w0 = *(const ulonglong2*)(w0p + j);
        ulonglong2 w1 = *(const ulonglong2*)(w1p + j);
        ulonglong2 w2 = *(const ulonglong2*)(w2p + j);
        ulonglong2 w3 = *(const ulonglong2*)(w3p + j);
        #pragma unroll
        for (int r = 0; r < 4; ++r) {
            ulonglong2 q = *(const ulonglong2*)(qp + r*IS + j);
            acc[r][0] = fma2(q.x, w0.x, acc[r][0]);
            acc[r][1] = fma2(q.x, w1.x, acc[r][1]);
            acc[r][2] = fma2(q.x, w2.x, acc[r][2]);
            acc[r][3] = fma2(q.x, w3.x, acc[r][3]);
            acc[r][0] = fma2(q.y, w0.y, acc[r][0]);
            acc[r][1] = fma2(q.y, w1.y, acc[r][1]);
            acc[r][2] = fma2(q.y, w2.y, acc[r][2]);
            acc[r][3] = fma2(q.y, w3.y, acc[r][3]);
        }
    }
}

// ---------------- Kernel 1: cp.async-pipelined precompute --------------------
extern "C" __global__ void __launch_bounds__(256, 2)
k_pre(const int* __restrict__ X, const int* __restrict__ Q,
      const float* __restrict__ q_emb, const float* __restrict__ x_emb,
      const float* __restrict__ key_W,
      const float* __restrict__ p_W1, const float* __restrict__ p_b1,
      const float* __restrict__ e_W, const float* __restrict__ e_b,
      const float* __restrict__ a_W, const float* __restrict__ a_b)
{
    extern __shared__ float sm[];
    float* sIn = sm;
    float* sPb[2] = { sm + SM_IN, sm + SM_IN + SM_P };
    __shared__ int sIdx[NROWS];

    const int tid = threadIdx.x;
    const bool qk = blockIdx.x < 400;
    const int row0 = (qk ? blockIdx.x : blockIdx.x - 400) * NROWS;

    if (tid < NROWS) sIdx[tid] = (qk ? Q : X)[row0 + tid];
    __syncthreads();

    // async input gather (64 rows) + panel 0
    {
        const float* emb = qk ? q_emb : x_emb;
        #pragma unroll
        for (int s = 0; s < 8; ++s) {
            int i = tid + s*256;
            int r = i >> 5, j = (i & 31) << 2;
            cp16(&sIn[r*IS + j], &emb[sIdx[r]*HH + j]);
        }
    }

    const float* psrc[4];
    int pstr[4], P;
    if (qk) {
        psrc[0] = key_W;           pstr[0] = HH;
        psrc[1] = p_W1;            pstr[1] = 256;
        psrc[2] = p_W1 + 64*256;   pstr[2] = 256;
        P = 3;
    } else {
        psrc[0] = e_W;             pstr[0] = HH;
        psrc[1] = e_W + 64*HH;     pstr[1] = HH;
        psrc[2] = a_W;             pstr[2] = HH;
        psrc[3] = a_W + 64*HH;     pstr[3] = HH;
        P = 4;
    }
    cp_panel(sPb[0], psrc[0], pstr[0], tid);
    CP_COMMIT();

    const int cx = tid & 15;
    const int ry = tid >> 4;

    for (int p = 0; p < P; ++p) {
        CP_WAIT0();
        __syncthreads();
        if (p + 1 < P) {
            cp_panel(sPb[(p+1)&1], psrc[p+1], pstr[p+1], tid);
            CP_COMMIT();
        }

        u64 acc[4][4];
        gemm_panel(sIn, sPb[p&1], ry, cx, acc);

        if (qk) {
            if (p == 0) {
                // softmax over the 64 key columns
                #pragma unroll
                for (int r = 0; r < 4; ++r) {
                    float v[4];
                    #pragma unroll
                    for (int k = 0; k < 4; ++k) {
                        float2 f = unpack2(acc[r][k]);
                        v[k] = f.x + f.y;
                    }
                    float mx = fmaxf(fmaxf(v[0], v[1]), fmaxf(v[2], v[3]));
                    #pragma unroll
                    for (int off = 8; off >= 1; off >>= 1)
                        mx = fmaxf(mx, __shfl_xor_sync(0xffffffffu, mx, off));
                    float e0 = __expf(v[0]-mx), e1 = __expf(v[1]-mx);
                    float e2 = __expf(v[2]-mx), e3 = __expf(v[3]-mx);
                    float sum = (e0+e1) + (e2+e3);
                    #pragma unroll
                    for (int off = 8; off >= 1; off >>= 1)
                        sum += __shfl_xor_sync(0xffffffffu, sum, off);
                    float inv = __frcp_rn(sum);
                    float* o = &g_K[(row0 + ry*4 + r)*CC + cx];
                    o[0]  = e0*inv; o[16] = e1*inv; o[32] = e2*inv; o[48] = e3*inv;
                }
            } else {
                const int col0 = (p - 1) * 64;
                #pragma unroll
                for (int r = 0; r < 4; ++r) {
                    float* o = &g_Qp[(row0 + ry*4 + r)*HH + col0 + cx];
                    #pragma unroll
                    for (int k = 0; k < 4; ++k) {
                        float2 f = unpack2(acc[r][k]);
                        o[k*16] = f.x + f.y + p_b1[col0 + cx + k*16];
                    }
                }
            }
        } else {
            if (p < 2) {
                const int col0 = p * 64;
                #pragma unroll
                for (int r = 0; r < 4; ++r) {
                    float* o = &g_E[(row0 + ry*4 + r)*HH + col0 + cx];
                    #pragma unroll
                    for (int k = 0; k < 4; ++k) {
                        float2 f = unpack2(acc[r][k]);
                        o[k*16] = fast_sigmoid(f.x + f.y + e_b[col0 + cx + k*16]);
                    }
                }
            } else {
                const int col0 = (p - 2) * 64;
                #pragma unroll
                for (int r = 0; r < 4; ++r) {
                    float* o = &g_A[(row0 + ry*4 + r)*HH + col0 + cx];
                    #pragma unroll
                    for (int k = 0; k < 4; ++k) {
                        float2 f = unpack2(acc[r][k]);
                        o[k*16] = fast_tanh(f.x + f.y + a_b[col0 + cx + k*16]);
                    }
                }
            }
        }
    }
}

// ---------------- Kernel 2: the scan -----------------------------------------
// 256 blocks x 256 thr. block = (b, 64 h's). K staged in smem once per block.
// E/A software-pipelined 4 iterations deep to cover L2/DRAM latency.
extern "C" __global__ void __launch_bounds__(256, 2)
k_scan()
{
    extern __shared__ float sK[];     // 200 x 64

    const int tid  = threadIdx.x;
    const int b    = blockIdx.x >> 1;
    const int hblk = blockIdx.x & 1;

    {   // cooperative K stage (coalesced float4)
        const float4* src = (const float4*)(g_K + b*LL*CC);
        float4* dst = (float4*)sK;
        #pragma unroll 4
        for (int i = tid; i < LL*CC/4; i += 256) dst[i] = src[i];
    }
    __syncthreads();

    const int wid  = tid >> 5;
    const int lane = tid & 31;
    const int sub  = lane >> 2;
    const int g    = lane & 3;
    const int h    = hblk*64 + wid*8 + sub;

    const float* Ks = sK + g*16;
    const float* Eb = g_E + b*LL*HH + h;
    const float* Ab = g_A + b*LL*HH + h;
    float*       Rb = g_R + b*LL*HH + h;

    u64 m2[8];
    #pragma unroll
    for (int i = 0; i < 8; ++i) m2[i] = 0ull;

    // 4-deep rotating prefetch buffers for E/A (distance ~4 iters > L2 latency)
    float ebuf[4], abuf[4];
    #pragma unroll
    for (int i = 0; i < 4; ++i) {
        ebuf[i] = Eb[i*HH];
        abuf[i] = Ab[i*HH];
    }

    for (int tc = 0; tc < LL; tc += 4) {
        #pragma unroll
        for (int u = 0; u < 4; ++u) {
            const int t = tc + u;
            const float ec = ebuf[u], ac = abuf[u];

            // refill this slot with t+4 (clamped; issued early, consumed 4 iters later)
            const int tp = (t + 4 < LL) ? t + 4 : LL - 1;
            ebuf[u] = Eb[tp*HH];
            abuf[u] = Ab[tp*HH];

            u64 kc[8];
            {
                const ulonglong2* p = (const ulonglong2*)(Ks + t*CC);
                ulonglong2 a0 = p[0], a1 = p[1], a2 = p[2], a3 = p[3];
                kc[0]=a0.x; kc[1]=a0.y; kc[2]=a1.x; kc[3]=a1.y;
                kc[4]=a2.x; kc[5]=a2.y; kc[6]=a3.x; kc[7]=a3.y;
            }

            // dot: R_t = sum_c k*m  (uses m BEFORE update)
            u64 sA = 0ull, sB = 0ull;
            #pragma unroll
            for (int i = 0; i < 4; ++i) {
                sA = fma2(kc[i],   m2[i],   sA);
                sB = fma2(kc[i+4], m2[i+4], sB);
            }
            float2 fa = unpack2(sA), fb = unpack2(sB);
            float s = (fa.x + fa.y) + (fb.x + fb.y);
            s += __shfl_xor_sync(0xffffffffu, s, 1);
            s += __shfl_xor_sync(0xffffffffu, s, 2);
            if (g == 0) Rb[t*HH] = s;

            // update: m = m + k*(a - m*e)
            u64 nee = pack2(-ec, -ec);
            u64 aa2 = pack2( ac,  ac);
            #pragma unroll
            for (int i = 0; i < 8; ++i)
                m2[i] = fma2(kc[i], fma2(m2[i], nee, aa2), m2[i]);
        }
    }
}

// ---------------- Kernel 3: P = sigmoid(tanh(Qp + R@W1r.T) . pW2 + b2) -------
extern "C" __global__ void __launch_bounds__(256, 2)
k_out(const float* __restrict__ p_W1, const float* __restrict__ p_W2,
      const float* __restrict__ p_b2, float* __restrict__ out)
{
    extern __shared__ float sm[];
    float* sR = sm;             // 64 x 132
    float* sW = sm + SM_IN;     // 128 x 132 (W1r)
    __shared__ float sW2[HH];

    const int tid  = threadIdx.x;
    const int row0 = blockIdx.x * NROWS;

    if (tid < HH) sW2[tid] = p_W2[tid];
    for (int i = tid; i < NROWS*32; i += 256) {
        int r = i >> 5, j = (i & 31) << 2;
        *(float4*)&sR[r*IS + j] = *(const float4*)&g_R[(row0 + r)*HH + j];
    }
    for (int i = tid; i < HH*32; i += 256) {
        int r = i >> 5, j = (i & 31) << 2;
        *(float4*)&sW[r*IS + j] = *(const float4*)&p_W1[r*256 + 128 + j];
    }
    __syncthreads();

    const int cx = tid & 31, ry = tid >> 5;
    u64 acc[8][4];
    {
        #pragma unroll
        for (int r = 0; r < 8; ++r)
            #pragma unroll
            for (int k = 0; k < 4; ++k) acc[r][k] = 0ull;

        const float* w0p = sW + (cx      )*IS;
        const float* w1p = sW + (cx + 32 )*IS;
        const float* w2p = sW + (cx + 64 )*IS;
        const float* w3p = sW + (cx + 96 )*IS;
        const float* qp  = sR + ry*8*IS;

        #pragma unroll 4
        for (int j = 0; j < 128; j += 4) {
            ulonglong2 w0 = *(const ulonglong2*)(w0p + j);
            ulonglong2 w1 = *(const ulonglong2*)(w1p + j);
            ulonglong2 w2 = *(const ulonglong2*)(w2p + j);
            ulonglong2 w3 = *(const ulonglong2*)(w3p + j);
            #pragma unroll
            for (int r = 0; r < 8; ++r) {
                ulonglong2 q = *(const ulonglong2*)(qp + r*IS + j);
                acc[r][0] = fma2(q.x, w0.x, acc[r][0]);
                acc[r][1] = fma2(q.x, w1.x, acc[r][1]);
                acc[r][2] = fma2(q.x, w2.x, acc[r][2]);
                acc[r][3] = fma2(q.x, w3.x, acc[r][3]);
                acc[r][0] = fma2(q.y, w0.y, acc[r][0]);
                acc[r][1] = fma2(q.y, w1.y, acc[r][1]);
                acc[r][2] = fma2(q.y, w2.y, acc[r][2]);
                acc[r][3] = fma2(q.y, w3.y, acc[r][3]);
            }
        }
    }

    const float b2v = __ldg(p_b2);
    float w2c[4] = { sW2[cx], sW2[cx+32], sW2[cx+64], sW2[cx+96] };

    #pragma unroll
    for (int r = 0; r < 8; ++r) {
        int row = row0 + ry*8 + r;
        const float* qp = &g_Qp[row*HH + cx];
        float ps = 0.f;
        #pragma unroll
        for (int k = 0; k < 4; ++k) {
            float2 f = unpack2(acc[r][k]);
            ps = fmaf(fast_tanh(f.x + f.y + qp[k*32]), w2c[k], ps);
        }
        #pragma unroll
        for (int off = 16; off >= 1; off >>= 1)
            ps += __shfl_xor_sync(0xffffffffu, ps, off);
        if ((tid & 31) == 0)
            out[row] = fast_sigmoid(ps + b2v);
    }
}

// ---------------- launch ----------------
extern "C" void kernel_launch(void* const* d_in, const int* in_sizes, int n_in,
                              void* d_out, int out_size)
{
    const int*   X     = (const int*)  d_in[0];
    const int*   Q     = (const int*)  d_in[1];
    const float* q_emb = (const float*)d_in[2];
    const float* x_emb = (const float*)d_in[3];
    const float* key_W = (const float*)d_in[4];
    const float* p_W1  = (const float*)d_in[5];
    const float* p_b1  = (const float*)d_in[6];
    const float* p_W2  = (const float*)d_in[7];
    const float* p_b2  = (const float*)d_in[8];
    const float* e_W   = (const float*)d_in[9];
    const float* e_b   = (const float*)d_in[10];
    const float* a_W   = (const float*)d_in[11];
    const float* a_b   = (const float*)d_in[12];
    float* out = (float*)d_out;

    static int configured = 0;
    if (!configured) {
        cudaFuncSetAttribute(k_pre,  cudaFuncAttributeMaxDynamicSharedMemorySize, PRE_SMEM);
        cudaFuncSetAttribute(k_scan, cudaFuncAttributeMaxDynamicSharedMemorySize, SCAN_SMEM);
        cudaFuncSetAttribute(k_out,  cudaFuncAttributeMaxDynamicSharedMemorySize, OUT_SMEM);
        configured = 1;
    }

    k_pre <<<800, 256, PRE_SMEM>>>(X, Q, q_emb, x_emb, key_W,
                                   p_W1, p_b1, e_W, e_b, a_W, a_b);
    k_scan<<<BB*2, 256, SCAN_SMEM>>>();
    k_out <<<400, 256, OUT_SMEM>>>(p_W1, p_W2, p_b2, out);
}

// round 11
// speedup vs baseline: 1.2553x; 1.2134x over previous
#include <cuda_runtime.h>
#include <cstdint>

#define BB 128
#define LL 200
#define HH 128
#define CC 64

#define IS 132                    // smem stride: 4 mod 32 -> conflict-free frag loads
#define NROWS 64
#define SM_IN  (NROWS*IS)         // input tile floats
#define SM_P   (64*IS)            // one 64-row weight panel
#define PRE_SMEM ((SM_IN + 2*SM_P) * 4)          // 101376 B -> 2 CTAs/SM
#define SM_W   (HH*IS)
#define OUT_SMEM ((SM_IN + SM_W) * 4)            // 101376 B
#define SCAN_SMEM (LL*CC*4)                      // 51200 B

typedef unsigned long long u64;

// ---- scratch (static device globals; no allocations) ----
__device__ float g_K [BB*LL*CC];
__device__ float g_Qp[BB*LL*HH];
__device__ float g_E [BB*LL*HH];
__device__ float g_A [BB*LL*HH];
__device__ float g_R [BB*LL*HH];

__device__ __forceinline__ u64 fma2(u64 a, u64 b, u64 c) {
    u64 d; asm("fma.rn.f32x2 %0, %1, %2, %3;" : "=l"(d) : "l"(a), "l"(b), "l"(c));
    return d;
}
__device__ __forceinline__ float2 unpack2(u64 a) {
    float2 f; asm("mov.b64 {%0, %1}, %2;" : "=f"(f.x), "=f"(f.y) : "l"(a));
    return f;
}
__device__ __forceinline__ u64 pack2(float lo, float hi) {
    u64 d; asm("mov.b64 %0, {%1, %2};" : "=l"(d) : "f"(lo), "f"(hi));
    return d;
}
__device__ __forceinline__ float fast_tanh(float x) {
    float y; asm("tanh.approx.f32 %0, %1;" : "=f"(y) : "f"(x)); return y;
}
__device__ __forceinline__ float fast_sigmoid(float x) {
    return 1.f / (1.f + __expf(-x));
}
__device__ __forceinline__ uint32_t f2tf(float x) {
    uint32_t r; asm("cvt.rna.tf32.f32 %0, %1;" : "=r"(r) : "f"(x)); return r;
}
__device__ __forceinline__ void mma_tf32(float d[4],
                                         uint32_t a0, uint32_t a1, uint32_t a2, uint32_t a3,
                                         uint32_t b0, uint32_t b1) {
    asm volatile(
        "mma.sync.aligned.m16n8k8.row.col.f32.tf32.tf32.f32 "
        "{%0,%1,%2,%3}, {%4,%5,%6,%7}, {%8,%9}, {%0,%1,%2,%3};\n"
        : "+f"(d[0]), "+f"(d[1]), "+f"(d[2]), "+f"(d[3])
        : "r"(a0), "r"(a1), "r"(a2), "r"(a3), "r"(b0), "r"(b1));
}
__device__ __forceinline__ void cp16(float* smem_dst, const float* gsrc) {
    uint32_t s = (uint32_t)__cvta_generic_to_shared(smem_dst);
    asm volatile("cp.async.ca.shared.global [%0], [%1], 16;" :: "r"(s), "l"(gsrc));
}
#define CP_COMMIT() asm volatile("cp.async.commit_group;")
#define CP_WAIT0()  asm volatile("cp.async.wait_group 0;" ::: "memory")

// async-copy one 64x128 weight panel (row stride `stride`) into smem stride IS
// (128-thread version)
__device__ __forceinline__ void cp_panel(float* dst, const float* __restrict__ src,
                                         int stride, int tid)
{
    #pragma unroll
    for (int s = 0; s < 16; ++s) {
        int i = tid + s*128;
        int r = i >> 5, j = (i & 31) << 2;
        cp16(&dst[r*IS + j], &src[r*stride + j]);
    }
}

// ---------------- Kernel 1: tf32 mma.sync precompute -------------------------
// 800 blocks x 128 thr (4 warps). Warp w: rows w*16..w*16+15, all 64 panel cols.
// Each panel: 16 k-tiles x 8 n-tiles of m16n8k8 tf32 mma.
extern "C" __global__ void __launch_bounds__(128, 2)
k_pre(const int* __restrict__ X, const int* __restrict__ Q,
      const float* __restrict__ q_emb, const float* __restrict__ x_emb,
      const float* __restrict__ key_W,
      const float* __restrict__ p_W1, const float* __restrict__ p_b1,
      const float* __restrict__ e_W, const float* __restrict__ e_b,
      const float* __restrict__ a_W, const float* __restrict__ a_b)
{
    extern __shared__ float sm[];
    float* sIn = sm;
    float* sPb[2] = { sm + SM_IN, sm + SM_IN + SM_P };
    __shared__ int sIdx[NROWS];

    const int tid = threadIdx.x;
    const bool qk = blockIdx.x < 400;
    const int row0 = (qk ? blockIdx.x : blockIdx.x - 400) * NROWS;

    if (tid < NROWS) sIdx[tid] = (qk ? Q : X)[row0 + tid];
    __syncthreads();

    // async input gather (64 rows x 128)
    {
        const float* emb = qk ? q_emb : x_emb;
        #pragma unroll
        for (int s = 0; s < 16; ++s) {
            int i = tid + s*128;
            int r = i >> 5, j = (i & 31) << 2;
            cp16(&sIn[r*IS + j], &emb[sIdx[r]*HH + j]);
        }
    }

    const float* psrc[4];
    int pstr[4], P;
    if (qk) {
        psrc[0] = key_W;           pstr[0] = HH;
        psrc[1] = p_W1;            pstr[1] = 256;
        psrc[2] = p_W1 + 64*256;   pstr[2] = 256;
        P = 3;
    } else {
        psrc[0] = e_W;             pstr[0] = HH;
        psrc[1] = e_W + 64*HH;     pstr[1] = HH;
        psrc[2] = a_W;             pstr[2] = HH;
        psrc[3] = a_W + 64*HH;     pstr[3] = HH;
        P = 4;
    }
    cp_panel(sPb[0], psrc[0], pstr[0], tid);
    CP_COMMIT();

    const int lane = tid & 31;
    const int warp = tid >> 5;        // 4 warps = 4 m-tiles of 16 rows
    const int g    = lane >> 2;       // 0..7
    const int tig  = lane & 3;        // 0..3
    const int mrow = warp * 16;

    for (int p = 0; p < P; ++p) {
        CP_WAIT0();
        __syncthreads();
        if (p + 1 < P) {
            cp_panel(sPb[(p+1)&1], psrc[p+1], pstr[p+1], tid);
            CP_COMMIT();
        }

        const float* sP = sPb[p&1];
        float acc[8][4];
        #pragma unroll
        for (int nt = 0; nt < 8; ++nt)
            #pragma unroll
            for (int c = 0; c < 4; ++c) acc[nt][c] = 0.f;

        // A fragment rows: mrow+g / mrow+g+8; cols k0+tig / k0+tig+4
        const float* aBase0 = sIn + (mrow + g    )*IS + tig;
        const float* aBase1 = sIn + (mrow + g + 8)*IS + tig;
        const float* bBase  = sP  + g*IS + tig;   // + nt*8*IS + k0

        #pragma unroll
        for (int kt = 0; kt < 16; ++kt) {
            const int k0 = kt * 8;
            uint32_t a0 = f2tf(aBase0[k0    ]);
            uint32_t a1 = f2tf(aBase1[k0    ]);
            uint32_t a2 = f2tf(aBase0[k0 + 4]);
            uint32_t a3 = f2tf(aBase1[k0 + 4]);
            #pragma unroll
            for (int nt = 0; nt < 8; ++nt) {
                uint32_t b0 = f2tf(bBase[nt*8*IS + k0    ]);
                uint32_t b1 = f2tf(bBase[nt*8*IS + k0 + 4]);
                mma_tf32(acc[nt], a0, a1, a2, a3, b0, b1);
            }
        }

        // ---- epilogues ----
        const int r0 = row0 + mrow + g;
        const int r1 = r0 + 8;
        const int cBase = 2*tig;      // col within n-tile: 2tig, 2tig+1

        if (qk && p == 0) {
            // softmax over 64 key columns; rows r0 (acc[][0..1]) and r1 (acc[][2..3])
            float mx0 = -1e30f, mx1 = -1e30f;
            #pragma unroll
            for (int nt = 0; nt < 8; ++nt) {
                mx0 = fmaxf(mx0, fmaxf(acc[nt][0], acc[nt][1]));
                mx1 = fmaxf(mx1, fmaxf(acc[nt][2], acc[nt][3]));
            }
            mx0 = fmaxf(mx0, __shfl_xor_sync(0xffffffffu, mx0, 1));
            mx0 = fmaxf(mx0, __shfl_xor_sync(0xffffffffu, mx0, 2));
            mx1 = fmaxf(mx1, __shfl_xor_sync(0xffffffffu, mx1, 1));
            mx1 = fmaxf(mx1, __shfl_xor_sync(0xffffffffu, mx1, 2));

            float ex[8][4];
            float s0 = 0.f, s1 = 0.f;
            #pragma unroll
            for (int nt = 0; nt < 8; ++nt) {
                ex[nt][0] = __expf(acc[nt][0] - mx0);
                ex[nt][1] = __expf(acc[nt][1] - mx0);
                ex[nt][2] = __expf(acc[nt][2] - mx1);
                ex[nt][3] = __expf(acc[nt][3] - mx1);
                s0 += ex[nt][0] + ex[nt][1];
                s1 += ex[nt][2] + ex[nt][3];
            }
            s0 += __shfl_xor_sync(0xffffffffu, s0, 1);
            s0 += __shfl_xor_sync(0xffffffffu, s0, 2);
            s1 += __shfl_xor_sync(0xffffffffu, s1, 1);
            s1 += __shfl_xor_sync(0xffffffffu, s1, 2);
            float i0 = __frcp_rn(s0), i1 = __frcp_rn(s1);

            #pragma unroll
            for (int nt = 0; nt < 8; ++nt) {
                int col = nt*8 + cBase;
                *(float2*)&g_K[r0*CC + col] = make_float2(ex[nt][0]*i0, ex[nt][1]*i0);
                *(float2*)&g_K[r1*CC + col] = make_float2(ex[nt][2]*i1, ex[nt][3]*i1);
            }
        } else if (qk) {
            const int col0 = (p - 1) * 64;
            #pragma unroll
            for (int nt = 0; nt < 8; ++nt) {
                int col = col0 + nt*8 + cBase;
                float2 bv = *(const float2*)&p_b1[col];
                *(float2*)&g_Qp[r0*HH + col] =
                    make_float2(acc[nt][0] + bv.x, acc[nt][1] + bv.y);
                *(float2*)&g_Qp[r1*HH + col] =
                    make_float2(acc[nt][2] + bv.x, acc[nt][3] + bv.y);
            }
        } else if (p < 2) {
            const int col0 = p * 64;
            #pragma unroll
            for (int nt = 0; nt < 8; ++nt) {
                int col = col0 + nt*8 + cBase;
                float2 bv = *(const float2*)&e_b[col];
                *(float2*)&g_E[r0*HH + col] =
                    make_float2(fast_sigmoid(acc[nt][0] + bv.x),
                                fast_sigmoid(acc[nt][1] + bv.y));
                *(float2*)&g_E[r1*HH + col] =
                    make_float2(fast_sigmoid(acc[nt][2] + bv.x),
                                fast_sigmoid(acc[nt][3] + bv.y));
            }
        } else {
            const int col0 = (p - 2) * 64;
            #pragma unroll
            for (int nt = 0; nt < 8; ++nt) {
                int col = col0 + nt*8 + cBase;
                float2 bv = *(const float2*)&a_b[col];
                *(float2*)&g_A[r0*HH + col] =
                    make_float2(fast_tanh(acc[nt][0] + bv.x),
                                fast_tanh(acc[nt][1] + bv.y));
                *(float2*)&g_A[r1*HH + col] =
                    make_float2(fast_tanh(acc[nt][2] + bv.x),
                                fast_tanh(acc[nt][3] + bv.y));
            }
        }
    }
}

// ---------------- Kernel 2: the scan (unchanged from passing R10) ------------
extern "C" __global__ void __launch_bounds__(256, 2)
k_scan()
{
    extern __shared__ float sK[];     // 200 x 64

    const int tid  = threadIdx.x;
    const int b    = blockIdx.x >> 1;
    const int hblk = blockIdx.x & 1;

    {   // cooperative K stage (coalesced float4)
        const float4* src = (const float4*)(g_K + b*LL*CC);
        float4* dst = (float4*)sK;
        #pragma unroll 4
        for (int i = tid; i < LL*CC/4; i += 256) dst[i] = src[i];
    }
    __syncthreads();

    const int wid  = tid >> 5;
    const int lane = tid & 31;
    const int sub  = lane >> 2;
    const int g    = lane & 3;
    const int h    = hblk*64 + wid*8 + sub;

    const float* Ks = sK + g*16;
    const float* Eb = g_E + b*LL*HH + h;
    const float* Ab = g_A + b*LL*HH + h;
    float*       Rb = g_R + b*LL*HH + h;

    u64 m2[8];
    #pragma unroll
    for (int i = 0; i < 8; ++i) m2[i] = 0ull;

    float ebuf[4], abuf[4];
    #pragma unroll
    for (int i = 0; i < 4; ++i) {
        ebuf[i] = Eb[i*HH];
        abuf[i] = Ab[i*HH];
    }

    for (int tc = 0; tc < LL; tc += 4) {
        #pragma unroll
        for (int u = 0; u < 4; ++u) {
            const int t = tc + u;
            const float ec = ebuf[u], ac = abuf[u];

            const int tp = (t + 4 < LL) ? t + 4 : LL - 1;
            ebuf[u] = Eb[tp*HH];
            abuf[u] = Ab[tp*HH];

            u64 kc[8];
            {
                const ulonglong2* p = (const ulonglong2*)(Ks + t*CC);
                ulonglong2 a0 = p[0], a1 = p[1], a2 = p[2], a3 = p[3];
                kc[0]=a0.x; kc[1]=a0.y; kc[2]=a1.x; kc[3]=a1.y;
                kc[4]=a2.x; kc[5]=a2.y; kc[6]=a3.x; kc[7]=a3.y;
            }

            u64 sA = 0ull, sB = 0ull;
            #pragma unroll
            for (int i = 0; i < 4; ++i) {
                sA = fma2(kc[i],   m2[i],   sA);
                sB = fma2(kc[i+4], m2[i+4], sB);
            }
            float2 fa = unpack2(sA), fb = unpack2(sB);
            float s = (fa.x + fa.y) + (fb.x + fb.y);
            s += __shfl_xor_sync(0xffffffffu, s, 1);
            s += __shfl_xor_sync(0xffffffffu, s, 2);
            if (g == 0) Rb[t*HH] = s;

            u64 nee = pack2(-ec, -ec);
            u64 aa2 = pack2( ac,  ac);
            #pragma unroll
            for (int i = 0; i < 8; ++i)
                m2[i] = fma2(kc[i], fma2(m2[i], nee, aa2), m2[i]);
        }
    }
}

// ---------------- Kernel 3: P = sigmoid(tanh(Qp + R@W1r.T) . pW2 + b2) -------
extern "C" __global__ void __launch_bounds__(256, 2)
k_out(const float* __restrict__ p_W1, const float* __restrict__ p_W2,
      const float* __restrict__ p_b2, float* __restrict__ out)
{
    extern __shared__ float sm[];
    float* sR = sm;             // 64 x 132
    float* sW = sm + SM_IN;     // 128 x 132 (W1r)
    __shared__ float sW2[HH];

    const int tid  = threadIdx.x;
    const int row0 = blockIdx.x * NROWS;

    if (tid < HH) sW2[tid] = p_W2[tid];
    for (int i = tid; i < NROWS*32; i += 256) {
        int r = i >> 5, j = (i & 31) << 2;
        *(float4*)&sR[r*IS + j] = *(const float4*)&g_R[(row0 + r)*HH + j];
    }
    for (int i = tid; i < HH*32; i += 256) {
        int r = i >> 5, j = (i & 31) << 2;
        *(float4*)&sW[r*IS + j] = *(const float4*)&p_W1[r*256 + 128 + j];
    }
    __syncthreads();

    const int cx = tid & 31, ry = tid >> 5;
    u64 acc[8][4];
    {
        #pragma unroll
        for (int r = 0; r < 8; ++r)
            #pragma unroll
            for (int k = 0; k < 4; ++k) acc[r][k] = 0ull;

        const float* w0p = sW + (cx      )*IS;
        const float* w1p = sW + (cx + 32 )*IS;
        const float* w2p = sW + (cx + 64 )*IS;
        const float* w3p = sW + (cx + 96 )*IS;
        const float* qp  = sR + ry*8*IS;

        #pragma unroll 4
        for (int j = 0; j < 128; j += 4) {
            ulonglong2 w0 = *(const ulonglong2*)(w0p + j);
            ulonglong2 w1 = *(const ulonglong2*)(w1p + j);
            ulonglong2 w2 = *(const ulonglong2*)(w2p + j);
            ulonglong2 w3 = *(const ulonglong2*)(w3p + j);
            #pragma unroll
            for (int r = 0; r < 8; ++r) {
                ulonglong2 q = *(const ulonglong2*)(qp + r*IS + j);
                acc[r][0] = fma2(q.x, w0.x, acc[r][0]);
                acc[r][1] = fma2(q.x, w1.x, acc[r][1]);
                acc[r][2] = fma2(q.x, w2.x, acc[r][2]);
                acc[r][3] = fma2(q.x, w3.x, acc[r][3]);
                acc[r][0] = fma2(q.y, w0.y, acc[r][0]);
                acc[r][1] = fma2(q.y, w1.y, acc[r][1]);
                acc[r][2] = fma2(q.y, w2.y, acc[r][2]);
                acc[r][3] = fma2(q.y, w3.y, acc[r][3]);
            }
        }
    }

    const float b2v = __ldg(p_b2);
    float w2c[4] = { sW2[cx], sW2[cx+32], sW2[cx+64], sW2[cx+96] };

    #pragma unroll
    for (int r = 0; r < 8; ++r) {
        int row = row0 + ry*8 + r;
        const float* qp = &g_Qp[row*HH + cx];
        float ps = 0.f;
        #pragma unroll
        for (int k = 0; k < 4; ++k) {
            float2 f = unpack2(acc[r][k]);
            ps = fmaf(fast_tanh(f.x + f.y + qp[k*32]), w2c[k], ps);
        }
        #pragma unroll
        for (int off = 16; off >= 1; off >>= 1)
            ps += __shfl_xor_sync(0xffffffffu, ps, off);
        if ((tid & 31) == 0)
            out[row] = fast_sigmoid(ps + b2v);
    }
}

// ---------------- launch ----------------
extern "C" void kernel_launch(void* const* d_in, const int* in_sizes, int n_in,
                              void* d_out, int out_size)
{
    const int*   X     = (const int*)  d_in[0];
    const int*   Q     = (const int*)  d_in[1];
    const float* q_emb = (const float*)d_in[2];
    const float* x_emb = (const float*)d_in[3];
    const float* key_W = (const float*)d_in[4];
    const float* p_W1  = (const float*)d_in[5];
    const float* p_b1  = (const float*)d_in[6];
    const float* p_W2  = (const float*)d_in[7];
    const float* p_b2  = (const float*)d_in[8];
    const float* e_W   = (const float*)d_in[9];
    const float* e_b   = (const float*)d_in[10];
    const float* a_W   = (const float*)d_in[11];
    const float* a_b   = (const float*)d_in[12];
    float* out = (float*)d_out;

    static int configured = 0;
    if (!configured) {
        cudaFuncSetAttribute(k_pre,  cudaFuncAttributeMaxDynamicSharedMemorySize, PRE_SMEM);
        cudaFuncSetAttribute(k_scan, cudaFuncAttributeMaxDynamicSharedMemorySize, SCAN_SMEM);
        cudaFuncSetAttribute(k_out,  cudaFuncAttributeMaxDynamicSharedMemorySize, OUT_SMEM);
        configured = 1;
    }

    k_pre <<<800, 128, PRE_SMEM>>>(X, Q, q_emb, x_emb, key_W,
                                   p_W1, p_b1, e_W, e_b, a_W, a_b);
    k_scan<<<BB*2, 256, SCAN_SMEM>>>();
    k_out <<<400, 256, OUT_SMEM>>>(p_W1, p_W2, p_b2, out);
}

// round 13
// speedup vs baseline: 1.5042x; 1.1983x over previous
#include <cuda_runtime.h>
#include <cstdint>

#define BB 128
#define LL 200
#define HH 128
#define CC 64

#define IS 132                    // smem stride: 4 mod 32
#define NROWS 64
#define SM_IN  (NROWS*IS)         // input tile floats
#define SM_P   (64*IS)            // one 64-row weight panel
#define PRE_SMEM ((SM_IN + 2*SM_P) * 4)          // 101376 B -> 2 CTAs/SM
#define SM_W   (HH*IS)
#define OUT_SMEM ((SM_IN + SM_W) * 4)            // 101376 B
#define SCAN_SMEM (LL*CC*4)                      // 51200 B

typedef unsigned long long u64;

// ---- scratch (static device globals; no allocations) ----
__device__ float g_K [BB*LL*CC];
__device__ float g_Qp[BB*LL*HH];
__device__ float g_E [BB*LL*HH];
__device__ float g_A [BB*LL*HH];
__device__ float g_R [BB*LL*HH];

__device__ __forceinline__ u64 fma2(u64 a, u64 b, u64 c) {
    u64 d; asm("fma.rn.f32x2 %0, %1, %2, %3;" : "=l"(d) : "l"(a), "l"(b), "l"(c));
    return d;
}
__device__ __forceinline__ float2 unpack2(u64 a) {
    float2 f; asm("mov.b64 {%0, %1}, %2;" : "=f"(f.x), "=f"(f.y) : "l"(a));
    return f;
}
__device__ __forceinline__ u64 pack2(float lo, float hi) {
    u64 d; asm("mov.b64 %0, {%1, %2};" : "=l"(d) : "f"(lo), "f"(hi));
    return d;
}
__device__ __forceinline__ float fast_tanh(float x) {
    float y; asm("tanh.approx.f32 %0, %1;" : "=f"(y) : "f"(x)); return y;
}
__device__ __forceinline__ float fast_sigmoid(float x) {
    return 1.f / (1.f + __expf(-x));
}
// raw f32 bits as tf32 operand (hardware truncates mantissa; no cvt cost)
__device__ __forceinline__ uint32_t f2r(float x) { return __float_as_uint(x); }

__device__ __forceinline__ void mma_tf32(float d[4],
                                         uint32_t a0, uint32_t a1, uint32_t a2, uint32_t a3,
                                         uint32_t b0, uint32_t b1) {
    asm volatile(
        "mma.sync.aligned.m16n8k8.row.col.f32.tf32.tf32.f32 "
        "{%0,%1,%2,%3}, {%4,%5,%6,%7}, {%8,%9}, {%0,%1,%2,%3};\n"
        : "+f"(d[0]), "+f"(d[1]), "+f"(d[2]), "+f"(d[3])
        : "r"(a0), "r"(a1), "r"(a2), "r"(a3), "r"(b0), "r"(b1));
}
__device__ __forceinline__ void cp16(float* smem_dst, const float* gsrc) {
    uint32_t s = (uint32_t)__cvta_generic_to_shared(smem_dst);
    asm volatile("cp.async.ca.shared.global [%0], [%1], 16;" :: "r"(s), "l"(gsrc));
}
#define CP_COMMIT() asm volatile("cp.async.commit_group;")
#define CP_WAIT0()  asm volatile("cp.async.wait_group 0;" ::: "memory")

// async-copy one 64x128 weight panel into smem stride IS (256 threads)
__device__ __forceinline__ void cp_panel(float* dst, const float* __restrict__ src,
                                         int stride, int tid)
{
    #pragma unroll
    for (int s = 0; s < 8; ++s) {
        int i = tid + s*256;
        int r = i >> 5, j = (i & 31) << 2;
        cp16(&dst[r*IS + j], &src[r*stride + j]);
    }
}

// ---------------- Kernel 1: tf32 mma precompute (256 thr) --------------------
// 8 warps: warp = (m-tile of 16 rows) x (32-col n-half of the 64-col panel).
extern "C" __global__ void __launch_bounds__(256, 2)
k_pre(const int* __restrict__ X, const int* __restrict__ Q,
      const float* __restrict__ q_emb, const float* __restrict__ x_emb,
      const float* __restrict__ key_W,
      const float* __restrict__ p_W1, const float* __restrict__ p_b1,
      const float* __restrict__ e_W, const float* __restrict__ e_b,
      const float* __restrict__ a_W, const float* __restrict__ a_b)
{
    extern __shared__ float sm[];
    float* sIn = sm;
    float* sPb[2] = { sm + SM_IN, sm + SM_IN + SM_P };
    __shared__ int sIdx[NROWS];
    __shared__ float sSum[NROWS*2];

    const int tid = threadIdx.x;
    const bool qk = blockIdx.x < 400;
    const int row0 = (qk ? blockIdx.x : blockIdx.x - 400) * NROWS;

    if (tid < NROWS) sIdx[tid] = (qk ? Q : X)[row0 + tid];
    __syncthreads();

    {   // async input gather (64 rows x 128)
        const float* emb = qk ? q_emb : x_emb;
        #pragma unroll
        for (int s = 0; s < 8; ++s) {
            int i = tid + s*256;
            int r = i >> 5, j = (i & 31) << 2;
            cp16(&sIn[r*IS + j], &emb[sIdx[r]*HH + j]);
        }
    }

    const float* psrc[4];
    int pstr[4], P;
    if (qk) {
        psrc[0] = key_W;           pstr[0] = HH;
        psrc[1] = p_W1;            pstr[1] = 256;
        psrc[2] = p_W1 + 64*256;   pstr[2] = 256;
        P = 3;
    } else {
        psrc[0] = e_W;             pstr[0] = HH;
        psrc[1] = e_W + 64*HH;     pstr[1] = HH;
        psrc[2] = a_W;             pstr[2] = HH;
        psrc[3] = a_W + 64*HH;     pstr[3] = HH;
        P = 4;
    }
    cp_panel(sPb[0], psrc[0], pstr[0], tid);
    CP_COMMIT();

    const int lane  = tid & 31;
    const int warp  = tid >> 5;
    const int g     = lane >> 2;       // 0..7
    const int tig   = lane & 3;        // 0..3
    const int mrow  = (warp >> 1) * 16;
    const int nbase = (warp & 1) * 32; // col half of 64-col panel

    for (int p = 0; p < P; ++p) {
        CP_WAIT0();
        __syncthreads();
        if (p + 1 < P) {
            cp_panel(sPb[(p+1)&1], psrc[p+1], pstr[p+1], tid);
            CP_COMMIT();
        }

        const float* sP = sPb[p&1];
        float acc[4][4];
        #pragma unroll
        for (int nt = 0; nt < 4; ++nt)
            #pragma unroll
            for (int c = 0; c < 4; ++c) acc[nt][c] = 0.f;

        const float* aBase0 = sIn + (mrow + g)*IS + tig;
        const float* aBase1 = aBase0 + 8*IS;
        const float* bBase  = sP + (nbase + g)*IS + tig;

        #pragma unroll
        for (int kt = 0; kt < 16; ++kt) {
            const int k0 = kt * 8;
            uint32_t a0 = f2r(aBase0[k0    ]);
            uint32_t a1 = f2r(aBase1[k0    ]);
            uint32_t a2 = f2r(aBase0[k0 + 4]);
            uint32_t a3 = f2r(aBase1[k0 + 4]);
            #pragma unroll
            for (int nt = 0; nt < 4; ++nt) {
                uint32_t b0 = f2r(bBase[nt*8*IS + k0    ]);
                uint32_t b1 = f2r(bBase[nt*8*IS + k0 + 4]);
                mma_tf32(acc[nt], a0, a1, a2, a3, b0, b1);
            }
        }

        const int r0 = row0 + mrow + g;
        const int r1 = r0 + 8;
        const int cBase = 2*tig;

        if (qk && p == 0) {
            // softmax over 64 cols, no max-sub (logits ~N(0,0.03)); cross-warp sum via smem
            float ex[4][4];
            float s0 = 0.f, s1 = 0.f;
            #pragma unroll
            for (int nt = 0; nt < 4; ++nt) {
                ex[nt][0] = __expf(acc[nt][0]);
                ex[nt][1] = __expf(acc[nt][1]);
                ex[nt][2] = __expf(acc[nt][2]);
                ex[nt][3] = __expf(acc[nt][3]);
                s0 += ex[nt][0] + ex[nt][1];
                s1 += ex[nt][2] + ex[nt][3];
            }
            s0 += __shfl_xor_sync(0xffffffffu, s0, 1);
            s0 += __shfl_xor_sync(0xffffffffu, s0, 2);
            s1 += __shfl_xor_sync(0xffffffffu, s1, 1);
            s1 += __shfl_xor_sync(0xffffffffu, s1, 2);
            if (tig == 0) {
                sSum[(mrow + g    )*2 + (warp & 1)] = s0;
                sSum[(mrow + g + 8)*2 + (warp & 1)] = s1;
            }
            __syncthreads();
            float i0 = __frcp_rn(sSum[(mrow + g    )*2] + sSum[(mrow + g    )*2 + 1]);
            float i1 = __frcp_rn(sSum[(mrow + g + 8)*2] + sSum[(mrow + g + 8)*2 + 1]);
            #pragma unroll
            for (int nt = 0; nt < 4; ++nt) {
                int col = nbase + nt*8 + cBase;
                *(float2*)&g_K[r0*CC + col] = make_float2(ex[nt][0]*i0, ex[nt][1]*i0);
                *(float2*)&g_K[r1*CC + col] = make_float2(ex[nt][2]*i1, ex[nt][3]*i1);
            }
        } else if (qk) {
            const int col0 = (p - 1) * 64 + nbase;
            #pragma unroll
            for (int nt = 0; nt < 4; ++nt) {
                int col = col0 + nt*8 + cBase;
                float2 bv = *(const float2*)&p_b1[col];
                *(float2*)&g_Qp[r0*HH + col] =
                    make_float2(acc[nt][0] + bv.x, acc[nt][1] + bv.y);
                *(float2*)&g_Qp[r1*HH + col] =
                    make_float2(acc[nt][2] + bv.x, acc[nt][3] + bv.y);
            }
        } else if (p < 2) {
            const int col0 = p * 64 + nbase;
            #pragma unroll
            for (int nt = 0; nt < 4; ++nt) {
                int col = col0 + nt*8 + cBase;
                float2 bv = *(const float2*)&e_b[col];
                *(float2*)&g_E[r0*HH + col] =
                    make_float2(fast_sigmoid(acc[nt][0] + bv.x),
                                fast_sigmoid(acc[nt][1] + bv.y));
                *(float2*)&g_E[r1*HH + col] =
                    make_float2(fast_sigmoid(acc[nt][2] + bv.x),
                                fast_sigmoid(acc[nt][3] + bv.y));
            }
        } else {
            const int col0 = (p - 2) * 64 + nbase;
            #pragma unroll
            for (int nt = 0; nt < 4; ++nt) {
                int col = col0 + nt*8 + cBase;
                float2 bv = *(const float2*)&a_b[col];
                *(float2*)&g_A[r0*HH + col] =
                    make_float2(fast_tanh(acc[nt][0] + bv.x),
                                fast_tanh(acc[nt][1] + bv.y));
                *(float2*)&g_A[r1*HH + col] =
                    make_float2(fast_tanh(acc[nt][2] + bv.x),
                                fast_tanh(acc[nt][3] + bv.y));
            }
        }
    }
}

// ---------------- Kernel 2: the scan (unchanged, passing) --------------------
extern "C" __global__ void __launch_bounds__(256, 2)
k_scan()
{
    extern __shared__ float sK[];     // 200 x 64

    const int tid  = threadIdx.x;
    const int b    = blockIdx.x >> 1;
    const int hblk = blockIdx.x & 1;

    {
        const float4* src = (const float4*)(g_K + b*LL*CC);
        float4* dst = (float4*)sK;
        #pragma unroll 4
        for (int i = tid; i < LL*CC/4; i += 256) dst[i] = src[i];
    }
    __syncthreads();

    const int wid  = tid >> 5;
    const int lane = tid & 31;
    const int sub  = lane >> 2;
    const int g    = lane & 3;
    const int h    = hblk*64 + wid*8 + sub;

    const float* Ks = sK + g*16;
    const float* Eb = g_E + b*LL*HH + h;
    const float* Ab = g_A + b*LL*HH + h;
    float*       Rb = g_R + b*LL*HH + h;

    u64 m2[8];
    #pragma unroll
    for (int i = 0; i < 8; ++i) m2[i] = 0ull;

    float ebuf[4], abuf[4];
    #pragma unroll
    for (int i = 0; i < 4; ++i) {
        ebuf[i] = Eb[i*HH];
        abuf[i] = Ab[i*HH];
    }

    for (int tc = 0; tc < LL; tc += 4) {
        #pragma unroll
        for (int u = 0; u < 4; ++u) {
            const int t = tc + u;
            const float ec = ebuf[u], ac = abuf[u];

            const int tp = (t + 4 < LL) ? t + 4 : LL - 1;
            ebuf[u] = Eb[tp*HH];
            abuf[u] = Ab[tp*HH];

            u64 kc[8];
            {
                const ulonglong2* p = (const ulonglong2*)(Ks + t*CC);
                ulonglong2 a0 = p[0], a1 = p[1], a2 = p[2], a3 = p[3];
                kc[0]=a0.x; kc[1]=a0.y; kc[2]=a1.x; kc[3]=a1.y;
                kc[4]=a2.x; kc[5]=a2.y; kc[6]=a3.x; kc[7]=a3.y;
            }

            u64 sA = 0ull, sB = 0ull;
            #pragma unroll
            for (int i = 0; i < 4; ++i) {
                sA = fma2(kc[i],   m2[i],   sA);
                sB = fma2(kc[i+4], m2[i+4], sB);
            }
            float2 fa = unpack2(sA), fb = unpack2(sB);
            float s = (fa.x + fa.y) + (fb.x + fb.y);
            s += __shfl_xor_sync(0xffffffffu, s, 1);
            s += __shfl_xor_sync(0xffffffffu, s, 2);
            if (g == 0) Rb[t*HH] = s;

            u64 nee = pack2(-ec, -ec);
            u64 aa2 = pack2( ac,  ac);
            #pragma unroll
            for (int i = 0; i < 8; ++i)
                m2[i] = fma2(kc[i], fma2(m2[i], nee, aa2), m2[i]);
        }
    }
}

// ---------------- Kernel 3: tf32 mma output ----------------------------------
// 400 blocks x 128 thr (4 warps). Warp = 16 rows x 128 cols (16 n-tiles).
extern "C" __global__ void __launch_bounds__(128, 2)
k_out(const float* __restrict__ p_W1, const float* __restrict__ p_W2,
      const float* __restrict__ p_b2, float* __restrict__ out)
{
    extern __shared__ float sm[];
    float* sR = sm;             // 64 x 132
    float* sW = sm + SM_IN;     // 128 x 132 (W1r)
    __shared__ float sW2[HH];

    const int tid  = threadIdx.x;
    const int row0 = blockIdx.x * NROWS;

    sW2[tid] = p_W2[tid];
    for (int i = tid; i < NROWS*32; i += 128) {
        int r = i >> 5, j = (i & 31) << 2;
        *(float4*)&sR[r*IS + j] = *(const float4*)&g_R[(row0 + r)*HH + j];
    }
    for (int i = tid; i < HH*32; i += 128) {
        int r = i >> 5, j = (i & 31) << 2;
        *(float4*)&sW[r*IS + j] = *(const float4*)&p_W1[r*256 + 128 + j];
    }
    __syncthreads();

    const int lane = tid & 31;
    const int warp = tid >> 5;
    const int g    = lane >> 2;
    const int tig  = lane & 3;
    const int mrow = warp * 16;

    float acc[16][4];
    #pragma unroll
    for (int nt = 0; nt < 16; ++nt)
        #pragma unroll
        for (int c = 0; c < 4; ++c) acc[nt][c] = 0.f;

    const float* aBase0 = sR + (mrow + g)*IS + tig;
    const float* aBase1 = aBase0 + 8*IS;
    const float* bBase  = sW + g*IS + tig;

    #pragma unroll
    for (int kt = 0; kt < 16; ++kt) {
        const int k0 = kt * 8;
        uint32_t a0 = f2r(aBase0[k0    ]);
        uint32_t a1 = f2r(aBase1[k0    ]);
        uint32_t a2 = f2r(aBase0[k0 + 4]);
        uint32_t a3 = f2r(aBase1[k0 + 4]);
        #pragma unroll
        for (int nt = 0; nt < 16; ++nt) {
            uint32_t b0 = f2r(bBase[nt*8*IS + k0    ]);
            uint32_t b1 = f2r(bBase[nt*8*IS + k0 + 4]);
            mma_tf32(acc[nt], a0, a1, a2, a3, b0, b1);
        }
    }

    const float b2v = __ldg(p_b2);
    const int r0 = row0 + mrow + g;
    const int r1 = r0 + 8;
    float ps0 = 0.f, ps1 = 0.f;
    #pragma unroll
    for (int nt = 0; nt < 16; ++nt) {
        int col = nt*8 + 2*tig;
        float2 w2 = *(const float2*)&sW2[col];
        float2 q0 = *(const float2*)&g_Qp[r0*HH + col];
        float2 q1 = *(const float2*)&g_Qp[r1*HH + col];
        ps0 = fmaf(fast_tanh(acc[nt][0] + q0.x), w2.x, ps0);
        ps0 = fmaf(fast_tanh(acc[nt][1] + q0.y), w2.y, ps0);
        ps1 = fmaf(fast_tanh(acc[nt][2] + q1.x), w2.x, ps1);
        ps1 = fmaf(fast_tanh(acc[nt][3] + q1.y), w2.y, ps1);
    }
    ps0 += __shfl_xor_sync(0xffffffffu, ps0, 1);
    ps0 += __shfl_xor_sync(0xffffffffu, ps0, 2);
    ps1 += __shfl_xor_sync(0xffffffffu, ps1, 1);
    ps1 += __shfl_xor_sync(0xffffffffu, ps1, 2);
    if (tig == 0) {
        out[r0] = fast_sigmoid(ps0 + b2v);
        out[r1] = fast_sigmoid(ps1 + b2v);
    }
}

// ---------------- launch ----------------
extern "C" void kernel_launch(void* const* d_in, const int* in_sizes, int n_in,
                              void* d_out, int out_size)
{
    const int*   X     = (const int*)  d_in[0];
    const int*   Q     = (const int*)  d_in[1];
    const float* q_emb = (const float*)d_in[2];
    const float* x_emb = (const float*)d_in[3];
    const float* key_W = (const float*)d_in[4];
    const float* p_W1  = (const float*)d_in[5];
    const float* p_b1  = (const float*)d_in[6];
    const float* p_W2  = (const float*)d_in[7];
    const float* p_b2  = (const float*)d_in[8];
    const float* e_W   = (const float*)d_in[9];
    const float* e_b   = (const float*)d_in[10];
    const float* a_W   = (const float*)d_in[11];
    const float* a_b   = (const float*)d_in[12];
    float* out = (float*)d_out;

    static int configured = 0;
    if (!configured) {
        cudaFuncSetAttribute(k_pre,  cudaFuncAttributeMaxDynamicSharedMemorySize, PRE_SMEM);
        cudaFuncSetAttribute(k_scan, cudaFuncAttributeMaxDynamicSharedMemorySize, SCAN_SMEM);
        cudaFuncSetAttribute(k_out,  cudaFuncAttributeMaxDynamicSharedMemorySize, OUT_SMEM);
        configured = 1;
    }

    k_pre <<<800, 256, PRE_SMEM>>>(X, Q, q_emb, x_emb, key_W,
                                   p_W1, p_b1, e_W, e_b, a_W, a_b);
    k_scan<<<BB*2, 256, SCAN_SMEM>>>();
    k_out <<<400, 128, OUT_SMEM>>>(p_W1, p_W2, p_b2, out);
}